// round 1
// baseline (speedup 1.0000x reference)
#include <cuda_runtime.h>

// Problem shapes (fixed by setup_inputs)
#define RADIUS 3
constexpr int N_ = 2, C_ = 64, S_ = 4, H_ = 64, W_ = 44;
constexpr int B_ = N_ * S_;                    // 8
constexpr int P_ = H_ * W_;                    // 2816
constexpr int K_ = (2 * RADIUS + 1) * (2 * RADIUS + 1);  // 49

constexpr int TILE_Y   = 4;
constexpr int ROWS_SM  = TILE_Y + 2 * RADIUS;  // 10
constexpr int WPAD     = W_ + 2 * RADIUS;      // 50 (3 zero cols each side)
constexpr int NPIX     = TILE_Y * W_;          // 176 pixels per CTA
constexpr int NTHREADS = 192;
constexpr int F1_ELEMS = C_ * ROWS_SM * WPAD;  // 32000 floats (125 KB)
constexpr int F0_ELEMS = C_ * NPIX;            // 11264 floats (44 KB)
constexpr int SMEM_BYTES = (F1_ELEMS + F0_ELEMS) * (int)sizeof(float);  // 173056

__global__ __launch_bounds__(NTHREADS, 1)
void flow_kernel(const float* __restrict__ f0g, const float* __restrict__ f1g,
                 float* __restrict__ outg) {
    extern __shared__ float sm[];
    float* f1s = sm;               // [C][ROWS_SM][WPAD], zero-padded halo
    float* f0s = sm + F1_ELEMS;    // [C][NPIX]

    const int tid  = threadIdx.x;
    const int tile = blockIdx.x;   // 0..H/TILE_Y-1
    const int b    = blockIdx.y;   // 0..B-1  (b = ni*S + si)
    const int ni   = b >> 2;
    const int si   = b & 3;
    const int y0   = tile * TILE_Y;

    // batch base into (n, c, s, h, w) layout: ((ni*C + c)*S + si)*P + y*W + x
    const int base1 = ((ni * C_) * S_ + si) * P_;

    // ---- zero-fill f1 tile (halo padding: out-of-range rows and cols stay 0)
    for (int i = tid; i < F1_ELEMS; i += NTHREADS) f1s[i] = 0.0f;
    __syncthreads();

    // ---- stage f1 tile (10 rows with y-halo) into smem
    for (int i = tid; i < C_ * ROWS_SM * W_; i += NTHREADS) {
        int c   = i / (ROWS_SM * W_);
        int rem = i - c * (ROWS_SM * W_);
        int r   = rem / W_;
        int xx  = rem - r * W_;
        int gy  = y0 - RADIUS + r;
        if (gy >= 0 && gy < H_) {
            f1s[(c * ROWS_SM + r) * WPAD + xx + RADIUS] =
                f1g[base1 + c * (S_ * P_) + gy * W_ + xx];
        }
    }
    // ---- stage f0 tile into smem
    for (int i = tid; i < F0_ELEMS; i += NTHREADS) {
        int c  = i / NPIX;
        int pp = i - c * NPIX;
        f0s[i] = f0g[base1 + c * (S_ * P_) + y0 * W_ + pp];
    }
    __syncthreads();

    if (tid < NPIX) {
        const int xl = tid % W_;
        const int yl = tid / W_;
        const int gy = y0 + yl;

        float acc[K_];
        #pragma unroll
        for (int k = 0; k < K_; ++k) acc[k] = 0.0f;

        // Correlation: 49 taps x 64 channels. Padded smem -> branch-free.
        const float* bptr = f1s + yl * WPAD + xl;   // tap (dy,dx) at +dy*WPAD+dx
        #pragma unroll 2
        for (int c = 0; c < C_; ++c) {
            const float a   = f0s[c * NPIX + tid];
            const float* rp = bptr + c * (ROWS_SM * WPAD);
            #pragma unroll
            for (int dy = 0; dy < 7; ++dy) {
                #pragma unroll
                for (int dx = 0; dx < 7; ++dx) {
                    acc[dy * 7 + dx] = fmaf(a, rp[dy * WPAD + dx], acc[dy * 7 + dx]);
                }
            }
        }

        // Masked softmax over valid taps (scale 1/sqrt(64) = 0.125), then
        // expected offset = flow (base cancels since probs sum to 1).
        float m = -1e30f;
        #pragma unroll
        for (int dy = 0; dy < 7; ++dy) {
            const int  ty = gy + dy - RADIUS;
            const bool vy = (ty >= 0) && (ty < H_);
            #pragma unroll
            for (int dx = 0; dx < 7; ++dx) {
                const int  tx = xl + dx - RADIUS;
                const bool v  = vy && (tx >= 0) && (tx < W_);
                const float cv = acc[dy * 7 + dx] * 0.125f;
                if (v) m = fmaxf(m, cv);
            }
        }
        float sum = 0.0f, fx = 0.0f, fy = 0.0f;
        #pragma unroll
        for (int dy = 0; dy < 7; ++dy) {
            const int  ty = gy + dy - RADIUS;
            const bool vy = (ty >= 0) && (ty < H_);
            #pragma unroll
            for (int dx = 0; dx < 7; ++dx) {
                const int  tx = xl + dx - RADIUS;
                const bool v  = vy && (tx >= 0) && (tx < W_);
                const float e = v ? __expf(acc[dy * 7 + dx] * 0.125f - m) : 0.0f;
                sum += e;
                fx  += e * (float)(dx - RADIUS);
                fy  += e * (float)(dy - RADIUS);
            }
        }
        const float inv = 1.0f / sum;
        fx *= inv;
        fy *= inv;

        // Output layout (n, 2, s, h, w): ((ni*2 + j)*S + si)*P + gy*W + xl
        const int ob = ((ni * 2) * S_ + si) * P_ + gy * W_ + xl;
        outg[ob]           = fx;   // j=0: x component
        outg[ob + S_ * P_] = fy;   // j=1: y component
    }
}

extern "C" void kernel_launch(void* const* d_in, const int* in_sizes, int n_in,
                              void* d_out, int out_size) {
    const float* f0 = (const float*)d_in[0];
    const float* f1 = (const float*)d_in[1];
    float* out = (float*)d_out;

    // >48KB dynamic smem opt-in (idempotent, capture-safe; not a stream op)
    cudaFuncSetAttribute(flow_kernel,
                         cudaFuncAttributeMaxDynamicSharedMemorySize, SMEM_BYTES);

    dim3 grid(H_ / TILE_Y, B_);
    flow_kernel<<<grid, NTHREADS, SMEM_BYTES>>>(f0, f1, out);
}

// round 2
// speedup vs baseline: 1.2884x; 1.2884x over previous
#include <cuda_runtime.h>

// Shapes fixed by setup_inputs
#define RADIUS 3
constexpr int N_ = 2, C_ = 64, S_ = 4, H_ = 64, W_ = 44;
constexpr int B_ = N_ * S_;                    // 8
constexpr int P_ = H_ * W_;                    // 2816
constexpr int K_ = 49;

constexpr int TILE_Y   = 4;
constexpr int ROWS_SM  = TILE_Y + 2 * RADIUS;  // 10
constexpr int WPAD     = W_ + 2 * RADIUS;      // 50
constexpr int NPIX     = TILE_Y * W_;          // 176 pixels per CTA
constexpr int GSIZE    = 192;                  // threads per tap-group (176 active)
constexpr int NGROUP   = 4;                    // tap split: 13/12/12/12
constexpr int NTHREADS = GSIZE * NGROUP;       // 768 = 24 warps
constexpr int F1_ELEMS = C_ * ROWS_SM * WPAD;  // 32000 floats (125 KB)
constexpr int F0_ELEMS = C_ * NPIX;            // 11264 floats (44 KB)
constexpr int RED_ELEMS = NGROUP * GSIZE * 4;  // 3072 floats (12 KB)
constexpr int SMEM_BYTES = (F1_ELEMS + F0_ELEMS + RED_ELEMS) * (int)sizeof(float);

// Correlation over taps [KS,KE) + masked partial softmax stats for this group.
template <int KS, int KE>
__device__ __forceinline__ void do_group(const float* __restrict__ f1s,
                                         const float* __restrict__ f0s,
                                         int px, int gy, int xl, int yl,
                                         float& m, float& s, float& fx, float& fy) {
    constexpr int NK = KE - KS;
    float acc[NK];
    #pragma unroll
    for (int i = 0; i < NK; ++i) acc[i] = 0.0f;

    const float* rp = f1s + yl * WPAD + xl;   // tap k at +(k/7)*WPAD + k%7
    const float* ap = f0s + px;
    #pragma unroll 4
    for (int c = 0; c < C_; ++c) {
        const float a = ap[c * NPIX];
        #pragma unroll
        for (int k = KS; k < KE; ++k)
            acc[k - KS] = fmaf(a, rp[(k / 7) * WPAD + (k % 7)], acc[k - KS]);
        rp += ROWS_SM * WPAD;
    }

    // Partial masked softmax stats (unscaled max; 0.125 scale applied in exp)
    m = -1e30f;
    #pragma unroll
    for (int k = KS; k < KE; ++k) {
        const int dy = k / 7 - RADIUS, dx = k % 7 - RADIUS;
        const bool v = ((unsigned)(gy + dy) < (unsigned)H_) &&
                       ((unsigned)(xl + dx) < (unsigned)W_);
        if (v) m = fmaxf(m, acc[k - KS]);
    }
    s = fx = fy = 0.0f;
    #pragma unroll
    for (int k = KS; k < KE; ++k) {
        const int dy = k / 7 - RADIUS, dx = k % 7 - RADIUS;
        const bool v = ((unsigned)(gy + dy) < (unsigned)H_) &&
                       ((unsigned)(xl + dx) < (unsigned)W_);
        const float e = v ? __expf((acc[k - KS] - m) * 0.125f) : 0.0f;
        s  += e;
        fx += e * (float)dx;
        fy += e * (float)dy;
    }
}

__global__ __launch_bounds__(NTHREADS, 1)
void flow_kernel(const float* __restrict__ f0g, const float* __restrict__ f1g,
                 float* __restrict__ outg) {
    extern __shared__ float sm[];
    float* f1s = sm;                       // [C][ROWS_SM][WPAD] zero-padded halo
    float* f0s = sm + F1_ELEMS;            // [C][NPIX]
    float* red = f0s + F0_ELEMS;           // [NGROUP][GSIZE][4] partials

    const int tid  = threadIdx.x;
    const int g    = tid / GSIZE;          // tap group, uniform per warp (192=6 warps)
    const int px   = tid - g * GSIZE;      // pixel slot 0..191 (176 active)
    const int tile = blockIdx.x;
    const int b    = blockIdx.y;
    const int ni   = b >> 2;
    const int si   = b & 3;
    const int y0   = tile * TILE_Y;
    const int base1 = ((ni * C_) * S_ + si) * P_;

    // ---- zero-fill f1 tile (halo stays 0)
    for (int i = tid; i < F1_ELEMS; i += NTHREADS) f1s[i] = 0.0f;
    __syncthreads();

    // ---- stage f1 (10 rows w/ y-halo) and f0 into smem
    for (int i = tid; i < C_ * ROWS_SM * W_; i += NTHREADS) {
        int c   = i / (ROWS_SM * W_);
        int rem = i - c * (ROWS_SM * W_);
        int r   = rem / W_;
        int xx  = rem - r * W_;
        int gy  = y0 - RADIUS + r;
        if (gy >= 0 && gy < H_)
            f1s[(c * ROWS_SM + r) * WPAD + xx + RADIUS] =
                f1g[base1 + c * (S_ * P_) + gy * W_ + xx];
    }
    for (int i = tid; i < F0_ELEMS; i += NTHREADS) {
        int c  = i / NPIX;
        int pp = i - c * NPIX;
        f0s[i] = f0g[base1 + c * (S_ * P_) + y0 * W_ + pp];
    }
    __syncthreads();

    const int xl = px % W_;
    const int yl = px / W_;
    const int gy = y0 + yl;

    float m = -1e30f, s = 0.0f, fx = 0.0f, fy = 0.0f;
    if (px < NPIX) {
        if      (g == 0) do_group< 0, 13>(f1s, f0s, px, gy, xl, yl, m, s, fx, fy);
        else if (g == 1) do_group<13, 25>(f1s, f0s, px, gy, xl, yl, m, s, fx, fy);
        else if (g == 2) do_group<25, 37>(f1s, f0s, px, gy, xl, yl, m, s, fx, fy);
        else             do_group<37, 49>(f1s, f0s, px, gy, xl, yl, m, s, fx, fy);
    }
    // publish partials (16B-aligned float4 slots)
    reinterpret_cast<float4*>(red)[g * GSIZE + px] = make_float4(m, s, fx, fy);
    __syncthreads();

    // ---- group 0 combines the 4 partials and writes flow
    if (g == 0 && px < NPIX) {
        float4 p0 = reinterpret_cast<const float4*>(red)[0 * GSIZE + px];
        float4 p1 = reinterpret_cast<const float4*>(red)[1 * GSIZE + px];
        float4 p2 = reinterpret_cast<const float4*>(red)[2 * GSIZE + px];
        float4 p3 = reinterpret_cast<const float4*>(red)[3 * GSIZE + px];

        float M = fmaxf(fmaxf(p0.x, p1.x), fmaxf(p2.x, p3.x));  // finite: center tap valid
        float w0 = __expf((p0.x - M) * 0.125f);  // m=-1e30 -> exp(-inf)=0, s already 0
        float w1 = __expf((p1.x - M) * 0.125f);
        float w2 = __expf((p2.x - M) * 0.125f);
        float w3 = __expf((p3.x - M) * 0.125f);

        float S  = p0.y * w0 + p1.y * w1 + p2.y * w2 + p3.y * w3;
        float Fx = p0.z * w0 + p1.z * w1 + p2.z * w2 + p3.z * w3;
        float Fy = p0.w * w0 + p1.w * w1 + p2.w * w2 + p3.w * w3;
        const float inv = 1.0f / S;

        // out layout (n, 2, s, h, w)
        const int ob = ((ni * 2) * S_ + si) * P_ + gy * W_ + xl;
        outg[ob]           = Fx * inv;
        outg[ob + S_ * P_] = Fy * inv;
    }
}

extern "C" void kernel_launch(void* const* d_in, const int* in_sizes, int n_in,
                              void* d_out, int out_size) {
    const float* f0 = (const float*)d_in[0];
    const float* f1 = (const float*)d_in[1];
    float* out = (float*)d_out;

    cudaFuncSetAttribute(flow_kernel,
                         cudaFuncAttributeMaxDynamicSharedMemorySize, SMEM_BYTES);

    dim3 grid(H_ / TILE_Y, B_);
    flow_kernel<<<grid, NTHREADS, SMEM_BYTES>>>(f0, f1, out);
}

// round 3
// speedup vs baseline: 1.6342x; 1.2684x over previous
#include <cuda_runtime.h>

// Shapes fixed by setup_inputs
#define RADIUS 3
constexpr int N_ = 2, C_ = 64, S_ = 4, H_ = 64, W_ = 44;
constexpr int B_ = N_ * S_;                 // 8
constexpr int P_ = H_ * W_;                 // 2816
constexpr int SP_ = S_ * P_;                // channel stride in elements

constexpr int TILE_Y  = 4;
constexpr int ROWS_SM = TILE_Y + 2 * RADIUS;   // 10
constexpr int WPAD    = 56;                    // padded row: 28 8B-banks; 2*28 % 16 == 8 (conflict-free pairing)
constexpr int NPIX    = TILE_Y * W_;           // 176
constexpr int GSIZE   = 96;                    // 3 warps per tap-row group (88 active pairs)
constexpr int NGROUP  = 7;                     // one 7-tap window row per group
constexpr int NTHREADS = GSIZE * NGROUP;       // 672 = 21 warps

constexpr int F1_ELEMS = C_ * ROWS_SM * WPAD;  // 35840 floats (140 KB)
constexpr int F0_ELEMS = C_ * TILE_Y * WPAD;   // 14336 floats (56 KB), same 56-col stride
constexpr int RED_ELEMS = NGROUP * NPIX * 4;   // 4928 floats
constexpr int SMEM_BYTES = (F1_ELEMS + F0_ELEMS + RED_ELEMS) * (int)sizeof(float); // 220416

__global__ __launch_bounds__(NTHREADS, 1)
void flow_kernel(const float* __restrict__ f0g, const float* __restrict__ f1g,
                 float* __restrict__ outg) {
    extern __shared__ float sm[];
    float* f1s = sm;                       // [C][ROWS_SM][WPAD], halo cols/rows zero
    float* f0s = sm + F1_ELEMS;            // [C][TILE_Y][WPAD] (cols 0..43 valid)
    float* red = f0s + F0_ELEMS;           // [NGROUP][NPIX][4]

    const int tid  = threadIdx.x;
    const int g    = tid / GSIZE;          // tap row, dy = g-3 (uniform per warp)
    const int s    = tid - g * GSIZE;
    const int wv   = s >> 5;               // warp within group: x block
    const int lane = s & 31;
    // lane -> (yl, x) so each 16-lane phase = {yl, yl+2} x 8 x-values (bank-tiled)
    const int x    = wv * 8 + (lane & 7);              // x-pair index, active if < 22
    const int yl   = 2 * ((lane >> 3) & 1) + (lane >> 4);
    const bool active = (x < 22);

    const int tile = blockIdx.x;
    const int b    = blockIdx.y;
    const int ni   = b >> 2;
    const int si   = b & 3;
    const int y0   = tile * TILE_Y;
    const int base1 = ((ni * C_) * S_ + si) * P_;

    // ---- zero-fill f1 tile (halo stays 0)
    for (int i = tid; i < F1_ELEMS; i += NTHREADS) f1s[i] = 0.0f;
    __syncthreads();

    // ---- stage f1 (10 rows w/ y-halo, x halo of 3) and f0
    for (int i = tid; i < C_ * ROWS_SM * W_; i += NTHREADS) {
        int c   = i / (ROWS_SM * W_);
        int rem = i - c * (ROWS_SM * W_);
        int r   = rem / W_;
        int xx  = rem - r * W_;
        int gy  = y0 - RADIUS + r;
        if (gy >= 0 && gy < H_)
            f1s[(c * ROWS_SM + r) * WPAD + xx + RADIUS] =
                f1g[base1 + c * SP_ + gy * W_ + xx];
    }
    for (int i = tid; i < C_ * TILE_Y * W_; i += NTHREADS) {
        int c   = i / (TILE_Y * W_);
        int rem = i - c * (TILE_Y * W_);
        int yy  = rem / W_;
        int xx  = rem - yy * W_;
        f0s[(c * TILE_Y + yy) * WPAD + xx] =
            f0g[base1 + c * SP_ + (y0 + yy) * W_ + xx];
    }
    __syncthreads();

    if (active) {
        const int xl0 = 2 * x;             // first pixel of the pair
        const int gy  = y0 + yl;

        float acc0[7], acc1[7];
        #pragma unroll
        for (int d = 0; d < 7; ++d) { acc0[d] = 0.0f; acc1[d] = 0.0f; }

        // float2 views; per-channel bases in float2 units
        const float2* __restrict__ f1v = reinterpret_cast<const float2*>(f1s);
        const float2* __restrict__ f0v = reinterpret_cast<const float2*>(f0s);
        const int tapb = (yl + g) * (WPAD / 2) + x;   // + c*(ROWS_SM*WPAD/2)
        const int f0b  = yl * (WPAD / 2) + x;         // + c*(TILE_Y*WPAD/2)

        #pragma unroll 4
        for (int c = 0; c < C_; ++c) {
            const float2 t0 = f1v[tapb + c * (ROWS_SM * WPAD / 2) + 0];
            const float2 t1 = f1v[tapb + c * (ROWS_SM * WPAD / 2) + 1];
            const float2 t2 = f1v[tapb + c * (ROWS_SM * WPAD / 2) + 2];
            const float2 t3 = f1v[tapb + c * (ROWS_SM * WPAD / 2) + 3];
            const float2 a  = f0v[f0b  + c * (TILE_Y * WPAD / 2)];
            const float r0 = t0.x, r1 = t0.y, r2 = t1.x, r3 = t1.y;
            const float r4 = t2.x, r5 = t2.y, r6 = t3.x, r7 = t3.y;
            acc0[0] = fmaf(a.x, r0, acc0[0]);  acc1[0] = fmaf(a.y, r1, acc1[0]);
            acc0[1] = fmaf(a.x, r1, acc0[1]);  acc1[1] = fmaf(a.y, r2, acc1[1]);
            acc0[2] = fmaf(a.x, r2, acc0[2]);  acc1[2] = fmaf(a.y, r3, acc1[2]);
            acc0[3] = fmaf(a.x, r3, acc0[3]);  acc1[3] = fmaf(a.y, r4, acc1[3]);
            acc0[4] = fmaf(a.x, r4, acc0[4]);  acc1[4] = fmaf(a.y, r5, acc1[4]);
            acc0[5] = fmaf(a.x, r5, acc0[5]);  acc1[5] = fmaf(a.y, r6, acc1[5]);
            acc0[6] = fmaf(a.x, r6, acc0[6]);  acc1[6] = fmaf(a.y, r7, acc1[6]);
        }

        // Masked partial softmax stats for this window row (dy = g-3).
        const bool rowv = ((unsigned)(gy + g - RADIUS) < (unsigned)H_);
        #pragma unroll
        for (int j = 0; j < 2; ++j) {
            const int xl = xl0 + j;
            const float* acc = j ? acc1 : acc0;
            float m = -1e30f;
            #pragma unroll
            for (int d = 0; d < 7; ++d) {
                const bool v = rowv && ((unsigned)(xl + d - RADIUS) < (unsigned)W_);
                if (v) m = fmaxf(m, acc[d]);
            }
            float sum = 0.0f, fx = 0.0f;
            #pragma unroll
            for (int d = 0; d < 7; ++d) {
                const bool v = rowv && ((unsigned)(xl + d - RADIUS) < (unsigned)W_);
                const float e = v ? __expf((acc[d] - m) * 0.125f) : 0.0f;
                sum += e;
                fx  += e * (float)(d - RADIUS);
            }
            // fy partial = (g-3)*sum, recovered in the combiner.
            const int px = yl * W_ + xl;
            reinterpret_cast<float4*>(red)[g * NPIX + px] = make_float4(m, sum, fx, 0.0f);
        }
    }
    __syncthreads();

    // ---- combine 7 row-partials per pixel, write flow
    if (tid < NPIX) {
        const int px = tid;
        const int xl = px % W_;
        const int yl2 = px / W_;
        const int gy = y0 + yl2;

        float4 p[NGROUP];
        #pragma unroll
        for (int gg = 0; gg < NGROUP; ++gg)
            p[gg] = reinterpret_cast<const float4*>(red)[gg * NPIX + px];

        float M = p[0].x;
        #pragma unroll
        for (int gg = 1; gg < NGROUP; ++gg) M = fmaxf(M, p[gg].x);

        float S = 0.0f, FX = 0.0f, FY = 0.0f;
        #pragma unroll
        for (int gg = 0; gg < NGROUP; ++gg) {
            const float wg = __expf((p[gg].x - M) * 0.125f);  // empty row: m=-1e30 -> 0
            S  += p[gg].y * wg;
            FX += p[gg].z * wg;
            FY += p[gg].y * wg * (float)(gg - RADIUS);
        }
        const float inv = 1.0f / S;
        const int ob = ((ni * 2) * S_ + si) * P_ + gy * W_ + xl;
        outg[ob]       = FX * inv;
        outg[ob + SP_] = FY * inv;
    }
}

extern "C" void kernel_launch(void* const* d_in, const int* in_sizes, int n_in,
                              void* d_out, int out_size) {
    const float* f0 = (const float*)d_in[0];
    const float* f1 = (const float*)d_in[1];
    float* out = (float*)d_out;

    cudaFuncSetAttribute(flow_kernel,
                         cudaFuncAttributeMaxDynamicSharedMemorySize, SMEM_BYTES);

    dim3 grid(H_ / TILE_Y, B_);
    flow_kernel<<<grid, NTHREADS, SMEM_BYTES>>>(f0, f1, out);
}

// round 4
// speedup vs baseline: 2.1133x; 1.2932x over previous
#include <cuda_runtime.h>

// Shapes fixed by setup_inputs
#define RADIUS 3
constexpr int N_ = 2, C_ = 64, S_ = 4, H_ = 64, W_ = 44;
constexpr int P_  = H_ * W_;                // 2816
constexpr int SP_ = S_ * P_;                // 11264 (channel stride)

constexpr int TILE_Y  = 4;
constexpr int ROWS_SM = TILE_Y + 2 * RADIUS;   // 10
constexpr int WPAD    = 54;   // 27 8B-banks (odd) -> conflict-free tap LDS.64 phases
constexpr int W0PAD   = 48;   // f0 row pad: 12 16B-banks -> conflict-free LDS.128
constexpr int NPIX    = TILE_Y * W_;           // 176
constexpr int NQUAD   = 44;                    // 4 rows x 11 x-quads
constexpr int GSIZE   = 64;                    // 2 warps per (g,h) group, 44 active
constexpr int NGROUP  = 14;                    // 7 tap rows x 2 channel halves
constexpr int NTHREADS = GSIZE * NGROUP;       // 896 = 28 warps

constexpr int F1_ELEMS = C_ * ROWS_SM * WPAD;  // 34560 floats (135 KB)
constexpr int F0_ELEMS = C_ * TILE_Y * W0PAD;  // 12288 floats (48 KB)
constexpr int SMEM_BYTES = (F1_ELEMS + F0_ELEMS) * (int)sizeof(float); // 187392

__global__ __launch_bounds__(NTHREADS, 1)
void flow_kernel(const float* __restrict__ f0g, const float* __restrict__ f1g,
                 float* __restrict__ outg) {
    extern __shared__ float sm[];
    float* f1s = sm;                 // [C][ROWS_SM][WPAD], data at cols 3..46, halo 0
    float* f0s = sm + F1_ELEMS;      // [C][TILE_Y][W0PAD], data at cols 0..43
    // aliases (dead data reuse, guarded by syncs):
    float4* red4  = reinterpret_cast<float4*>(sm);             // [7][176] over f1s
    float4* exch4 = reinterpret_cast<float4*>(sm + F1_ELEMS);  // [308][7] over f0s

    const int tid  = threadIdx.x;
    const int grp  = tid >> 6;           // 0..13
    const int s    = tid & 63;           // lane-in-group
    const int h    = grp / 7;            // channel half
    const int g    = grp % 7;            // tap row, dy = g-3
    // lane -> (yl, qx): engineered for conflict-free LDS phases
    int yl, qx;
    if (s < 32) { yl = s >> 3;       qx = s & 7; }
    else        { int l = s - 32; yl = l / 3; qx = 8 + l % 3; }
    const bool active = (s < 44);

    const int b    = blockIdx.y;
    const int ni   = b >> 2;
    const int si   = b & 3;
    const int y0   = blockIdx.x * TILE_Y;
    const int base1 = ((ni * C_) * S_ + si) * P_;

    // ---- zero-fill f1 tile via float4 (halo cols/rows stay 0)
    {
        float4* f1s4 = reinterpret_cast<float4*>(f1s);
        for (int i = tid; i < F1_ELEMS / 4; i += NTHREADS)
            f1s4[i] = make_float4(0.f, 0.f, 0.f, 0.f);
    }
    __syncthreads();

    // ---- stage f1: 220 float2 slots/ch, div-free channel loop (16 ch/thread)
    const float2* __restrict__ f1g2 = reinterpret_cast<const float2*>(f1g);
    const float2* __restrict__ f0g2 = reinterpret_cast<const float2*>(f0g);
    if (tid < 880) {
        const int slot = tid % 220;
        const int chb  = (tid / 220) * 16;
        const int row  = slot / 22;
        const int xu   = slot % 22;
        const int gy   = y0 - RADIUS + row;
        if ((unsigned)gy < (unsigned)H_) {
            int src = (base1 + gy * W_) / 2 + xu + chb * (SP_ / 2);
            int dst = (chb * ROWS_SM + row) * WPAD + 3 + 2 * xu;
            #pragma unroll 4
            for (int k = 0; k < 16; ++k) {
                float2 v = f1g2[src];
                f1s[dst] = v.x; f1s[dst + 1] = v.y;   // odd col base: scalar STS
                src += SP_ / 2; dst += ROWS_SM * WPAD;
            }
        }
    }
    // ---- stage f0: 88 float2 slots/ch (8 ch/thread)
    if (tid < 704) {
        const int slot = tid % 88;
        const int chb  = (tid / 88) * 8;
        const int row  = slot / 22;
        const int xu   = slot % 22;
        int src = (base1 + (y0 + row) * W_) / 2 + xu + chb * (SP_ / 2);
        int dst = (chb * TILE_Y + row) * (W0PAD / 2) + xu;
        float2* __restrict__ f0s2 = reinterpret_cast<float2*>(f0s);
        #pragma unroll 4
        for (int k = 0; k < 8; ++k) {
            f0s2[dst] = f0g2[src];
            src += SP_ / 2; dst += TILE_Y * (W0PAD / 2);
        }
    }
    __syncthreads();

    // ---- main loop: 4 pixels x 7 taps x 32 channels
    float acc[28];
    #pragma unroll
    for (int i = 0; i < 28; ++i) acc[i] = 0.0f;

    if (active) {
        const float2* __restrict__ f1v = reinterpret_cast<const float2*>(f1s);
        const float4* __restrict__ f0q = reinterpret_cast<const float4*>(f0s);
        const float2* tap = f1v + ((h * 32) * ROWS_SM + yl + g) * (WPAD / 2) + 2 * qx;
        const float4* a4  = f0q + ((h * 32) * TILE_Y + yl) * (W0PAD / 4) + qx;

        #pragma unroll 2
        for (int c = 0; c < 32; ++c) {
            const float2 t0 = tap[0], t1 = tap[1], t2 = tap[2], t3 = tap[3], t4 = tap[4];
            const float4 A  = a4[0];
            const float r[10] = {t0.x, t0.y, t1.x, t1.y, t2.x,
                                 t2.y, t3.x, t3.y, t4.x, t4.y};
            const float a[4] = {A.x, A.y, A.z, A.w};
            #pragma unroll
            for (int p = 0; p < 4; ++p)
                #pragma unroll
                for (int d = 0; d < 7; ++d)
                    acc[p * 7 + d] = fmaf(a[p], r[p + d], acc[p * 7 + d]);
            tap += ROWS_SM * (WPAD / 2);
            a4  += TILE_Y * (W0PAD / 4);
        }
    }
    __syncthreads();   // all reads of f1s/f0s done; aliases become writable

    const int widx = g * NQUAD + (s < 32 ? s : 32 + (s - 32));  // == g*44 + slot
    if (active && h == 0) {
        #pragma unroll
        for (int j = 0; j < 7; ++j)
            exch4[widx * 7 + j] =
                make_float4(acc[4 * j], acc[4 * j + 1], acc[4 * j + 2], acc[4 * j + 3]);
    }
    __syncthreads();

    if (active && h == 1) {
        #pragma unroll
        for (int j = 0; j < 7; ++j) {
            const float4 e = exch4[widx * 7 + j];
            acc[4 * j]     += e.x; acc[4 * j + 1] += e.y;
            acc[4 * j + 2] += e.z; acc[4 * j + 3] += e.w;
        }
        // masked per-row softmax stats for dy = g-3
        const bool rowv = ((unsigned)(y0 + yl + g - RADIUS) < (unsigned)H_);
        const int xl0 = 4 * qx;
        #pragma unroll
        for (int p = 0; p < 4; ++p) {
            const int xl = xl0 + p;
            float m = -1e30f;
            #pragma unroll
            for (int d = 0; d < 7; ++d) {
                const bool v = rowv && ((unsigned)(xl + d - RADIUS) < (unsigned)W_);
                if (v) m = fmaxf(m, acc[p * 7 + d]);
            }
            float ss = 0.0f, fx = 0.0f;
            #pragma unroll
            for (int d = 0; d < 7; ++d) {
                const bool v = rowv && ((unsigned)(xl + d - RADIUS) < (unsigned)W_);
                const float e = v ? __expf((acc[p * 7 + d] - m) * 0.125f) : 0.0f;
                ss += e;
                fx += e * (float)(d - RADIUS);
            }
            red4[g * NPIX + yl * W_ + xl] = make_float4(m, ss, fx, 0.0f);
        }
    }
    __syncthreads();

    // ---- combine 7 row-partials per pixel
    if (tid < NPIX) {
        const int xl = tid % W_;
        const int yr = tid / W_;
        const int gy = y0 + yr;

        float4 p[7];
        #pragma unroll
        for (int gg = 0; gg < 7; ++gg) p[gg] = red4[gg * NPIX + tid];

        float M = p[0].x;
        #pragma unroll
        for (int gg = 1; gg < 7; ++gg) M = fmaxf(M, p[gg].x);

        float S = 0.0f, FX = 0.0f, FY = 0.0f;
        #pragma unroll
        for (int gg = 0; gg < 7; ++gg) {
            const float wg = __expf((p[gg].x - M) * 0.125f);  // empty row -> 0
            S  += p[gg].y * wg;
            FX += p[gg].z * wg;
            FY += p[gg].y * wg * (float)(gg - RADIUS);
        }
        const float inv = 1.0f / S;
        const int ob = ((ni * 2) * S_ + si) * P_ + gy * W_ + xl;
        outg[ob]       = FX * inv;
        outg[ob + SP_] = FY * inv;
    }
}

extern "C" void kernel_launch(void* const* d_in, const int* in_sizes, int n_in,
                              void* d_out, int out_size) {
    const float* f0 = (const float*)d_in[0];
    const float* f1 = (const float*)d_in[1];
    float* out = (float*)d_out;

    cudaFuncSetAttribute(flow_kernel,
                         cudaFuncAttributeMaxDynamicSharedMemorySize, SMEM_BYTES);

    dim3 grid(H_ / TILE_Y, N_ * S_);
    flow_kernel<<<grid, NTHREADS, SMEM_BYTES>>>(f0, f1, out);
}